// round 1
// baseline (speedup 1.0000x reference)
#include <cuda_runtime.h>
#include <cuda_bf16.h>
#include <cstddef>

// 1x1 conv as batched GEMM: out[b,o,p] = sum_i W[i,o] * x[b,i,p]
// B=32, CIN=COUT=128, P=H*W=16384.
// SGEMM tiling: per block, BM=128 (all COUT) x BN=128 pixels, BK=8.
// 256 threads, 8x8 micro-tile per thread (split 4+4 at stride 64 for
// conflict-free LDS.128), smem double-buffered with register prefetch.

#define CIN   128
#define COUT  128
#define HW    16384
#define BN    128
#define BK    8
#define NKT   (CIN / BK)

__global__ __launch_bounds__(256, 2)
void conv1x1_sgemm_kernel(const float* __restrict__ x,
                          const float* __restrict__ w,
                          float* __restrict__ out)
{
    __shared__ float As[2][BK][COUT];  // weight tile: As[k][o]
    __shared__ float Bs[2][BK][BN];    // x tile:      Bs[k][p]

    const int b  = blockIdx.y;
    const int p0 = blockIdx.x * BN;
    const int t  = threadIdx.x;

    const float* xb = x   + (size_t)b * CIN  * HW;
    float*       ob = out + (size_t)b * COUT * HW;

    // gmem->smem load mapping: 8 rows x 128 cols per tile, float4 per thread
    const int lrow = t >> 5;          // 0..7
    const int lcol = (t & 31) * 4;    // 0..124

    // first tile
    float4 wreg = *(const float4*)(w  + lrow * COUT + lcol);
    float4 xreg = *(const float4*)(xb + lrow * HW + p0 + lcol);
    *(float4*)&As[0][lrow][lcol] = wreg;
    *(float4*)&Bs[0][lrow][lcol] = xreg;
    __syncthreads();

    // compute mapping: thread handles o in {to..to+3, to+64..to+67},
    //                  p in {tp..tp+3, tp+64..tp+67}
    const int to = (t >> 4) * 4;      // 0..60
    const int tp = (t & 15) * 4;      // 0..60

    float acc[8][8] = {};

    int buf = 0;
    #pragma unroll 1
    for (int kt = 0; kt < NKT; kt++) {
        float4 wn, xn;
        const bool more = (kt + 1 < NKT);
        if (more) {
            wn = *(const float4*)(w  + ((kt + 1) * BK + lrow) * COUT + lcol);
            xn = *(const float4*)(xb + ((kt + 1) * BK + lrow) * HW + p0 + lcol);
        }

        #pragma unroll
        for (int k = 0; k < BK; k++) {
            float a[8], bb[8];
            *(float4*)&a[0]  = *(const float4*)&As[buf][k][to];
            *(float4*)&a[4]  = *(const float4*)&As[buf][k][to + 64];
            *(float4*)&bb[0] = *(const float4*)&Bs[buf][k][tp];
            *(float4*)&bb[4] = *(const float4*)&Bs[buf][k][tp + 64];
            #pragma unroll
            for (int i = 0; i < 8; i++)
                #pragma unroll
                for (int j = 0; j < 8; j++)
                    acc[i][j] = fmaf(a[i], bb[j], acc[i][j]);
        }

        if (more) {
            buf ^= 1;
            *(float4*)&As[buf][lrow][lcol] = wn;
            *(float4*)&Bs[buf][lrow][lcol] = xn;
            __syncthreads();
        }
    }

    // store 8x8 micro-tile: rows o, cols p (two float4 per row)
    #pragma unroll
    for (int i = 0; i < 8; i++) {
        const int o = to + ((i < 4) ? i : (60 + i));   // +64 offset for upper half
        float4 v0 = make_float4(acc[i][0], acc[i][1], acc[i][2], acc[i][3]);
        float4 v1 = make_float4(acc[i][4], acc[i][5], acc[i][6], acc[i][7]);
        *(float4*)(ob + (size_t)o * HW + p0 + tp)      = v0;
        *(float4*)(ob + (size_t)o * HW + p0 + tp + 64) = v1;
    }
}

extern "C" void kernel_launch(void* const* d_in, const int* in_sizes, int n_in,
                              void* d_out, int out_size)
{
    const float* x = (const float*)d_in[0];   // (32, 128, 128, 128) fp32
    const float* w = (const float*)d_in[1];   // (128, 128) fp32
    float* out = (float*)d_out;               // (32, 128, 128, 128) fp32

    dim3 grid(HW / BN, 32);   // 128 pixel-tiles x 32 batches
    dim3 block(256);
    conv1x1_sgemm_kernel<<<grid, block>>>(x, w, out);
}

// round 3
// speedup vs baseline: 2.2736x; 2.2736x over previous
#include <cuda_runtime.h>
#include <cstdint>
#include <cstddef>

// 1x1 conv as GEMM on HMMA (mma.sync tf32) — tcgen05 is unavailable because the
// harness lowers through a compute_103 (non-'a') PTX target.
// out[b,o,p] = sum_i W[i,o] * x[b,i,p];  B=32, CIN=COUT=128, HW=16384.
// Persistent kernel, 152 CTAs. Per tile: M=128(COUT) x N=128(px) x K=128(CIN).
// 8 warps, 2(M)x4(N), warp tile m64 x n32, mma.m16n8k8.tf32.
// W^T in SMEM once (k-pair-interleaved, pad 8 -> LDS.64 A frags, conflict-free).
// x double-buffered cp.async ([k][128+8] layout, conflict-free b frags).

#define HW      16384
#define NCH     128
#define TILE_N  128
#define NTILES  4096         // 32 batches * (16384/128) pixel tiles
#define GRID    152
#define NTHREADS 256
#define ROWW    136          // padded row width in floats (128 + 8)

#define A_OFF      0                      // 128*136 floats = 17408
#define B_OFF(s)   (17408 + (s) * 17408)  // two x buffers
#define SMEM_FLOATS (17408 * 3)
#define SMEM_BYTES  (SMEM_FLOATS * 4)     // 208896 B

__device__ __forceinline__ uint32_t smem_u32(const void* p) {
    uint32_t a;
    asm("{ .reg .u64 t; cvta.to.shared.u64 t, %1; cvt.u32.u64 %0, t; }" : "=r"(a) : "l"(p));
    return a;
}

#define CP_ASYNC16(smaddr, gptr) \
    asm volatile("cp.async.cg.shared.global [%0], [%1], 16;" \
        :: "r"(smaddr), "l"(__cvta_generic_to_global(gptr)) : "memory")
#define CP_COMMIT() asm volatile("cp.async.commit_group;" ::: "memory")
#define CP_WAIT1()  asm volatile("cp.async.wait_group 1;" ::: "memory")

__device__ __forceinline__ void mma_tf32(float c[4], uint32_t a0, uint32_t a1,
                                         uint32_t a2, uint32_t a3,
                                         uint32_t b0, uint32_t b1) {
    asm volatile(
        "mma.sync.aligned.m16n8k8.row.col.f32.tf32.tf32.f32 "
        "{%0,%1,%2,%3},{%4,%5,%6,%7},{%8,%9},{%0,%1,%2,%3};"
        : "+f"(c[0]), "+f"(c[1]), "+f"(c[2]), "+f"(c[3])
        : "r"(a0), "r"(a1), "r"(a2), "r"(a3), "r"(b0), "r"(b1));
}

__global__ __launch_bounds__(NTHREADS, 1)
void conv1x1_hmma_kernel(const float* __restrict__ x,
                         const float* __restrict__ w,
                         float* __restrict__ out)
{
    extern __shared__ __align__(16) float smem[];
    const uint32_t sb = smem_u32(smem);
    const int tid = threadIdx.x;
    const int lid = tid & 31;
    const int wid = tid >> 5;
    const int mw  = wid & 1;         // warp row (M dir): 0..1
    const int nw  = wid >> 1;        // warp col (N dir): 0..3
    const int bid = blockIdx.x;

    // ---- Load W^T into A smem once, RN-rounded to tf32.
    // A[m=o][k], k-pair interleaved: word = o*ROWW + (k/8)*8 + (k%4)*2 + ((k/4)&1)
    for (int i = tid; i < NCH * NCH; i += NTHREADS) {
        int k = i >> 7, o = i & 127;            // consecutive tid -> consecutive o (coalesced)
        float v = __ldg(&w[k * NCH + o]);
        uint32_t t;
        asm("cvt.rna.tf32.f32 %0, %1;" : "=r"(t) : "f"(v));
        smem[A_OFF + o * ROWW + (k >> 3) * 8 + (k & 3) * 2 + ((k >> 2) & 1)] = __uint_as_float(t);
    }
    __syncthreads();

    const int n = (NTILES - bid + GRID - 1) / GRID;

    // ---- x tile loader: 128 k-rows x 128 px -> [k][128+8] floats, 16B cp.async
    auto load_tile = [&](int i) {
        int t  = bid + i * GRID;
        int b  = t >> 7;
        int p0 = (t & 127) * TILE_N;
        const float* xb = x + (size_t)b * NCH * HW + p0;
        uint32_t base = sb + (uint32_t)B_OFF(i & 1) * 4u;
        #pragma unroll
        for (int c = 0; c < 16; c++) {
            int id  = tid + c * NTHREADS;       // 0..4095
            int row = id >> 5;                  // k row
            int off = (id & 31) * 4;            // float offset within row
            CP_ASYNC16(base + (uint32_t)(row * ROWW + off) * 4u,
                       xb + (size_t)row * HW + off);
        }
    };

    load_tile(0); CP_COMMIT();
    if (n > 1) load_tile(1);
    CP_COMMIT();

    const int lr = lid >> 2;   // 0..7
    const int lc = lid & 3;    // 0..3

    for (int i = 0; i < n; i++) {
        const int s = i & 1;
        CP_WAIT1();
        __syncthreads();

        const float* Asm = smem + A_OFF + (mw * 64 + lr) * ROWW + lc * 2;
        const float* Bsm = smem + B_OFF(s) + nw * 32 + lr;

        float acc[4][4][4];
        #pragma unroll
        for (int mt = 0; mt < 4; mt++)
            #pragma unroll
            for (int nt = 0; nt < 4; nt++)
                #pragma unroll
                for (int q = 0; q < 4; q++) acc[mt][nt][q] = 0.f;

        #pragma unroll 4
        for (int kk = 0; kk < 16; kk++) {
            uint32_t af[4][4];
            #pragma unroll
            for (int mt = 0; mt < 4; mt++) {
                const float* pa = Asm + mt * 16 * ROWW + kk * 8;
                asm volatile("ld.shared.v2.b32 {%0,%1}, [%2];"
                    : "=r"(af[mt][0]), "=r"(af[mt][2]) : "r"(smem_u32(pa)));
                asm volatile("ld.shared.v2.b32 {%0,%1}, [%2];"
                    : "=r"(af[mt][1]), "=r"(af[mt][3]) : "r"(smem_u32(pa + 8 * ROWW)));
            }
            uint32_t bf[4][2];
            #pragma unroll
            for (int nt = 0; nt < 4; nt++) {
                const float* pb = Bsm + (kk * 8 + lc) * ROWW + nt * 8;
                bf[nt][0] = __float_as_uint(pb[0]);
                bf[nt][1] = __float_as_uint(pb[4 * ROWW]);
            }
            #pragma unroll
            for (int mt = 0; mt < 4; mt++)
                #pragma unroll
                for (int nt = 0; nt < 4; nt++)
                    mma_tf32(acc[mt][nt], af[mt][0], af[mt][1], af[mt][2], af[mt][3],
                             bf[nt][0], bf[nt][1]);
        }

        __syncthreads();                 // all warps done reading buf s
        if (i + 2 < n) load_tile(i + 2);
        CP_COMMIT();

        // ---- epilogue: store 64x32 warp tile (overlaps cp.async of tile i+2)
        int t  = bid + i * GRID;
        int b  = t >> 7;
        int p0 = (t & 127) * TILE_N;
        float* ob = out + (size_t)b * NCH * HW + p0 + nw * 32 + lc * 2;
        #pragma unroll
        for (int mt = 0; mt < 4; mt++) {
            int o0 = mw * 64 + mt * 16 + lr;
            float* orow = ob + (size_t)o0 * HW;
            #pragma unroll
            for (int nt = 0; nt < 4; nt++) {
                *(float2*)(orow + nt * 8)          = make_float2(acc[mt][nt][0], acc[mt][nt][1]);
                *(float2*)(orow + 8 * HW + nt * 8) = make_float2(acc[mt][nt][2], acc[mt][nt][3]);
            }
        }
    }
}

extern "C" void kernel_launch(void* const* d_in, const int* in_sizes, int n_in,
                              void* d_out, int out_size)
{
    const float* x = (const float*)d_in[0];   // (32,128,128,128) fp32
    const float* w = (const float*)d_in[1];   // (128,128) fp32
    float* out = (float*)d_out;

    cudaFuncSetAttribute(conv1x1_hmma_kernel,
                         cudaFuncAttributeMaxDynamicSharedMemorySize, SMEM_BYTES);
    conv1x1_hmma_kernel<<<GRID, NTHREADS, SMEM_BYTES>>>(x, w, out);
}